// round 8
// baseline (speedup 1.0000x reference)
#include <cuda_runtime.h>
#include <cuda_bf16.h>
#include <cstdint>

// FourierCrossAttention: B=64, L=S=2048, H=8, E=64, MODES=64, O=64
// out[b,h,o,l] = irfft_l( scatter( w-contraction( tanh(Xq^T Xk) Xk ) ) ) / (512*512)

#define N_B   64
#define N_L   2048
#define N_H   8
#define N_E   64
#define N_M   64
#define N_HE  512
#define N_J   128   // 2*N_M, interleaved (re,im)

typedef unsigned long long ull;

// ---------- scratch (static device globals; no runtime alloc) ----------------
__device__ double2 g_twd[N_L];             // twiddle table cos,sin (double)
__device__ float g_Bf[N_L * N_J];          // forward basis [l][j]
__device__ float g_Bi[N_J * N_L];          // inverse basis [j][l] (coef folded)
__device__ float g_Xq[N_B * N_HE * N_J];
__device__ float g_Xk[N_B * N_HE * N_J];
__device__ float g_Spec[N_B * N_HE * N_J];

// ---------- packed f32x2 helpers ---------------------------------------------
__device__ __forceinline__ ull pk2(float lo, float hi) {
    ull r; asm("mov.b64 %0, {%1, %2};" : "=l"(r) : "f"(lo), "f"(hi)); return r;
}
__device__ __forceinline__ void fma2(ull &d, ull a, ull b) {
    asm("fma.rn.f32x2 %0, %1, %2, %0;" : "+l"(d) : "l"(a), "l"(b));
}
__device__ __forceinline__ void add2(ull &d, ull a) {
    asm("add.rn.f32x2 %0, %0, %1;" : "+l"(d) : "l"(a));
}

// ---------- K-1: twiddle table (only 2048 double sincos on the whole chip) ---
__global__ void k_tw() {
    int i = blockIdx.x * blockDim.x + threadIdx.x;   // 2048 threads
    double s, c;
    sincos((double)i * (6.283185307179586476925287 / 2048.0), &s, &c);
    g_twd[i] = make_double2(c, s);
}

// ---------- K0: basis tables (gather from table; no heavy math) --------------
__global__ void k_basis() {
    int idx = blockIdx.x * blockDim.x + threadIdx.x;   // 64*2048 threads
    int m = idx >> 11;
    int l = idx & 2047;
    double2 t = g_twd[(m * l) & 2047];
    g_Bf[l * N_J + 2 * m]     = (float)t.x;
    g_Bf[l * N_J + 2 * m + 1] = (float)(-t.y);
    double coef = (m == 0 ? 1.0 : 2.0) / (2048.0 * 512.0 * 512.0);
    g_Bi[(2 * m) * N_L + l]     = (float)(coef * t.x);
    g_Bi[(2 * m + 1) * N_L + l] = (m == 0) ? 0.0f : (float)(-coef * t.y);
}

// ---------- K1: truncated DFT as GEMM, K=2048 --------------------------------
// grid (4 he-tiles, 64 b, 2 {q,k}); 128 thr; block tile 128he x 64 pairs (all j)
// thread tile 8he x 8 pairs. A stored DUPLICATED in smem -> no pk2 in mainloop.
__global__ void __launch_bounds__(128) k_dft(const float* __restrict__ qp,
                                             const float* __restrict__ kp) {
    const float* src = blockIdx.z ? kp : qp;
    float* dst       = blockIdx.z ? g_Xk : g_Xq;
    int b = blockIdx.y;
    int he0 = blockIdx.x * 128;

    __shared__ __align__(16) float sA2[32][256];  // [l][2*he] duplicated pairs
    __shared__ __align__(16) float sB[32][128];   // [l][j]

    int t = threadIdx.x;
    int w = t >> 5, lane = t & 31;
    int tr = t >> 3, tc = t & 7;        // 16 x 8 thread grid
    int hs = tr * 8;                    // 8 he rows

    ull acc[8][8], accM[8][8];
#pragma unroll
    for (int i = 0; i < 8; i++)
#pragma unroll
        for (int q = 0; q < 8; q++) { acc[i][q] = 0ull; accM[i][q] = 0ull; }

    const float* abase = src + (size_t)b * N_L * N_HE + he0;

    for (int l0 = 0; l0 < N_L; l0 += 32) {
        // fill: each warp fills rows w, w+4, ..., w+28
#pragma unroll
        for (int rr = 0; rr < 8; rr++) {
            int row = w + rr * 4;
            float4 v = *(const float4*)(abase + (size_t)(l0 + row) * N_HE + lane * 4);
            ulonglong2 d0, d1;
            d0.x = pk2(v.x, v.x); d0.y = pk2(v.y, v.y);
            d1.x = pk2(v.z, v.z); d1.y = pk2(v.w, v.w);
            *(ulonglong2*)&sA2[row][lane * 8]     = d0;
            *(ulonglong2*)&sA2[row][lane * 8 + 4] = d1;
            *(float4*)&sB[row][lane * 4] =
                *(const float4*)(g_Bf + (size_t)(l0 + row) * N_J + lane * 4);
        }
        __syncthreads();
#pragma unroll 4
        for (int kk = 0; kk < 32; kk++) {
            ulonglong2 a01 = *(ulonglong2*)&sA2[kk][2 * hs];
            ulonglong2 a23 = *(ulonglong2*)&sA2[kk][2 * hs + 4];
            ulonglong2 a45 = *(ulonglong2*)&sA2[kk][2 * hs + 8];
            ulonglong2 a67 = *(ulonglong2*)&sA2[kk][2 * hs + 12];
            ull aa[8] = {a01.x, a01.y, a23.x, a23.y, a45.x, a45.y, a67.x, a67.y};
            ull bb[8];
#pragma unroll
            for (int i = 0; i < 8; i++)
                bb[i] = *(ull*)&sB[kk][2 * (tc + 8 * i)];
#pragma unroll
            for (int hi = 0; hi < 8; hi++)
#pragma unroll
                for (int i = 0; i < 8; i++)
                    fma2(acc[hi][i], aa[hi], bb[i]);
        }
        __syncthreads();
        if (((l0 >> 5) & 7) == 7) {   // flush every 256 l's: tames fp32 drift
#pragma unroll
            for (int i = 0; i < 8; i++)
#pragma unroll
                for (int q = 0; q < 8; q++) { add2(accM[i][q], acc[i][q]); acc[i][q] = 0ull; }
        }
    }
#pragma unroll
    for (int hi = 0; hi < 8; hi++) {
        float* dp = dst + (size_t)(b * N_HE + he0 + hs + hi) * N_J;
#pragma unroll
        for (int i = 0; i < 8; i++)
            *(ull*)&dp[2 * (tc + 8 * i)] = accM[hi][i];
    }
}

// ---------- complex tanh: fast saturated path + stable double fallback -------
__device__ __forceinline__ float2 ctanh_c(float re, float im) {
    if (fabsf(re) > 9.5f)                      // |tanh|=1 to fp32; im ~ 2e^-19
        return make_float2(re > 0.0f ? 1.0f : -1.0f, 0.0f);
    double tx = tanh((double)re);
    double ty = tan((double)im);
    double tx2 = tx * tx, ty2 = ty * ty;
    double inv = 1.0 / (1.0 + tx2 * ty2);
    return make_float2((float)(tx * (1.0 + ty2) * inv),
                       (float)(ty * (1.0 - tx2) * inv));
}

// ---------- K2: fused middle stage, one block per (b,h) ----------------------
#define K2_SMEM (3 * 64 * 66 * (int)sizeof(float2))
__global__ void __launch_bounds__(256, 2) k_mid(const float* __restrict__ w1r,
                                                const float* __restrict__ w1i) {
    int bh = blockIdx.x;
    int b = bh >> 3, h = bh & 7;
    extern __shared__ float2 sm2[];
    float2 (*sQ)[66] = (float2(*)[66])sm2;          // Xq[e][x] -> later Xqkv
    float2 (*sK)[66] = ((float2(*)[66])sm2) + 64;   // Xk[e][y]
    float2 (*sA)[66] = ((float2(*)[66])sm2) + 128;  // A[y][x]

    int t = threadIdx.x;
    int r = t >> 4, c = t & 15;
    int xs = c * 4;

    const float* xqb = g_Xq + (size_t)(b * N_HE + h * N_E) * N_J;
    const float* xkb = g_Xk + (size_t)(b * N_HE + h * N_E) * N_J;
    for (int i = t; i < 64 * 32; i += 256) {
        int row = i >> 5, c4 = i & 31;
        *(float4*)&sQ[row][c4 * 2] = *(const float4*)(xqb + row * N_J + c4 * 4);
        *(float4*)&sK[row][c4 * 2] = *(const float4*)(xkb + row * N_J + c4 * 4);
    }
    __syncthreads();

    // stage A: A[x][y] = tanh( sum_e Xq[e][x]*Xk[e][y] )   (no conjugate)
    {
        int ys = r * 4;
        float are[4][4] = {}, aim[4][4] = {};
        for (int e = 0; e < 64; e++) {
            float4 q0 = *(float4*)&sQ[e][xs];
            float4 q1 = *(float4*)&sQ[e][xs + 2];
            float qr[4] = {q0.x, q0.z, q1.x, q1.z};
            float qi[4] = {q0.y, q0.w, q1.y, q1.w};
            float4 k0 = *(float4*)&sK[e][ys];
            float4 k1 = *(float4*)&sK[e][ys + 2];
            float kr[4] = {k0.x, k0.z, k1.x, k1.z};
            float ki[4] = {k0.y, k0.w, k1.y, k1.w};
#pragma unroll
            for (int i = 0; i < 4; i++)
#pragma unroll
                for (int j = 0; j < 4; j++) {
                    are[i][j] = fmaf(qr[i], kr[j], are[i][j]);
                    are[i][j] = fmaf(-qi[i], ki[j], are[i][j]);
                    aim[i][j] = fmaf(qr[i], ki[j], aim[i][j]);
                    aim[i][j] = fmaf(qi[i], kr[j], aim[i][j]);
                }
        }
#pragma unroll
        for (int i = 0; i < 4; i++)
#pragma unroll
            for (int j = 0; j < 4; j++)
                sA[ys + j][xs + i] = ctanh_c(are[i][j], aim[i][j]);
    }
    __syncthreads();

    // stage B: Xqkv[e][x] = sum_y A[x][y]*Xk[e][y]   -> overwrite sQ
    {
        int es = r * 4;
        float vre[4][4] = {}, vim[4][4] = {};   // [e][x]
        for (int y = 0; y < 64; y++) {
            float4 a0 = *(float4*)&sA[y][xs];
            float4 a1 = *(float4*)&sA[y][xs + 2];
            float ar[4] = {a0.x, a0.z, a1.x, a1.z};
            float ai[4] = {a0.y, a0.w, a1.y, a1.w};
            float2 kv[4];
#pragma unroll
            for (int j = 0; j < 4; j++) kv[j] = sK[es + j][y];
#pragma unroll
            for (int ei = 0; ei < 4; ei++)
#pragma unroll
                for (int xi = 0; xi < 4; xi++) {
                    vre[ei][xi] = fmaf(ar[xi], kv[ei].x, vre[ei][xi]);
                    vre[ei][xi] = fmaf(-ai[xi], kv[ei].y, vre[ei][xi]);
                    vim[ei][xi] = fmaf(ar[xi], kv[ei].y, vim[ei][xi]);
                    vim[ei][xi] = fmaf(ai[xi], kv[ei].x, vim[ei][xi]);
                }
        }
        __syncthreads();
#pragma unroll
        for (int ei = 0; ei < 4; ei++)
#pragma unroll
            for (int xi = 0; xi < 4; xi++)
                sQ[es + ei][xs + xi] = make_float2(vre[ei][xi], vim[ei][xi]);
    }
    __syncthreads();

    // stage C: Spec[o][x] = sum_e Xqkv[e][x] * w[h,e,o,x]
    {
        int os = r * 4;
        float sre[4][4] = {}, sim_[4][4] = {};  // [o][x]
        for (int e = 0; e < 64; e++) {
            float4 x0 = *(float4*)&sQ[e][xs];
            float4 x1 = *(float4*)&sQ[e][xs + 2];
            float xr[4] = {x0.x, x0.z, x1.x, x1.z};
            float xi_[4] = {x0.y, x0.w, x1.y, x1.w};
            size_t wo = (((size_t)h * 64 + e) * 64 + os) * 64 + xs;
#pragma unroll
            for (int j = 0; j < 4; j++) {
                float4 w4r = *(const float4*)(w1r + wo + (size_t)j * 64);
                float4 w4i = *(const float4*)(w1i + wo + (size_t)j * 64);
                float wr[4] = {w4r.x, w4r.y, w4r.z, w4r.w};
                float wi[4] = {w4i.x, w4i.y, w4i.z, w4i.w};
#pragma unroll
                for (int i = 0; i < 4; i++) {
                    sre[j][i]  = fmaf(xr[i],  wr[i], sre[j][i]);
                    sre[j][i]  = fmaf(-xi_[i], wi[i], sre[j][i]);
                    sim_[j][i] = fmaf(xr[i],  wi[i], sim_[j][i]);
                    sim_[j][i] = fmaf(xi_[i], wr[i], sim_[j][i]);
                }
            }
        }
        float* sp = g_Spec + (size_t)(b * N_HE + h * N_E) * N_J;
#pragma unroll
        for (int j = 0; j < 4; j++)
#pragma unroll
            for (int i = 0; i < 4; i++)
                *(float2*)&sp[(os + j) * N_J + 2 * (xs + i)] =
                    make_float2(sre[j][i], sim_[j][i]);
    }
}

// ---------- K3: irfft as GEMM, K=128 -----------------------------------------
// grid (16 l-tiles, 256 row-tiles); 128 thr; block tile 128 rows x 128 l
// thread tile 8 rows x 8 l-pairs. Spec transposed + DUPLICATED in smem.
__global__ void __launch_bounds__(128) k_irfft(float* __restrict__ out) {
    int l0 = blockIdx.x * 128;
    int r0 = blockIdx.y * 128;

    __shared__ __align__(16) float sST2[32][256];  // [j][2*row] duplicated
    __shared__ __align__(16) float sB[32][128];    // [j][l]

    int t = threadIdx.x;
    int w = t >> 5, lane = t & 31;
    int tr = t >> 3, tc = t & 7;
    int hs = tr * 8;

    ull acc[8][8];
#pragma unroll
    for (int i = 0; i < 8; i++)
#pragma unroll
        for (int q = 0; q < 8; q++) acc[i][q] = 0ull;

    for (int j0 = 0; j0 < N_J; j0 += 32) {
        // Spec transpose+dup fill: thread t owns Spec row r0+t; STS.64 @ 8B*t
        {
            const float* gs = g_Spec + (size_t)(r0 + t) * N_J + j0;
#pragma unroll
            for (int u = 0; u < 8; u++) {
                float4 v = *(const float4*)(gs + u * 4);
                *(ull*)&sST2[u * 4 + 0][2 * t] = pk2(v.x, v.x);
                *(ull*)&sST2[u * 4 + 1][2 * t] = pk2(v.y, v.y);
                *(ull*)&sST2[u * 4 + 2][2 * t] = pk2(v.z, v.z);
                *(ull*)&sST2[u * 4 + 3][2 * t] = pk2(v.w, v.w);
            }
        }
        // Bi fill: warp-per-row, coalesced
#pragma unroll
        for (int rr = 0; rr < 8; rr++) {
            int row = w + rr * 4;
            *(float4*)&sB[row][lane * 4] =
                *(const float4*)(g_Bi + (size_t)(j0 + row) * N_L + l0 + lane * 4);
        }
        __syncthreads();
#pragma unroll 4
        for (int kk = 0; kk < 32; kk++) {
            ulonglong2 a01 = *(ulonglong2*)&sST2[kk][2 * hs];
            ulonglong2 a23 = *(ulonglong2*)&sST2[kk][2 * hs + 4];
            ulonglong2 a45 = *(ulonglong2*)&sST2[kk][2 * hs + 8];
            ulonglong2 a67 = *(ulonglong2*)&sST2[kk][2 * hs + 12];
            ull aa[8] = {a01.x, a01.y, a23.x, a23.y, a45.x, a45.y, a67.x, a67.y};
            ull bb[8];
#pragma unroll
            for (int i = 0; i < 8; i++)
                bb[i] = *(ull*)&sB[kk][2 * (tc + 8 * i)];
#pragma unroll
            for (int hi = 0; hi < 8; hi++)
#pragma unroll
                for (int i = 0; i < 8; i++)
                    fma2(acc[hi][i], aa[hi], bb[i]);
        }
        __syncthreads();
    }
#pragma unroll
    for (int hi = 0; hi < 8; hi++) {
        float* dp = out + (size_t)(r0 + hs + hi) * N_L + l0;
#pragma unroll
        for (int i = 0; i < 8; i++)
            *(ull*)&dp[2 * (tc + 8 * i)] = acc[hi][i];
    }
}

// ---------- launch ------------------------------------------------------------
extern "C" void kernel_launch(void* const* d_in, const int* in_sizes, int n_in,
                              void* d_out, int out_size) {
    const float* q   = (const float*)d_in[0];
    const float* k   = (const float*)d_in[1];
    const float* w1r = (const float*)d_in[3];
    const float* w1i = (const float*)d_in[4];
    float* out = (float*)d_out;

    cudaFuncSetAttribute(k_mid, cudaFuncAttributeMaxDynamicSharedMemorySize, K2_SMEM);

    k_tw<<<8, 256>>>();
    k_basis<<<512, 256>>>();
    dim3 g1(4, 64, 2);
    k_dft<<<g1, 128>>>(q, k);
    k_mid<<<512, 256, K2_SMEM>>>(w1r, w1i);
    dim3 g3(16, 256);
    k_irfft<<<g3, 128>>>(out);
}

// round 9
// speedup vs baseline: 1.8380x; 1.8380x over previous
#include <cuda_runtime.h>
#include <cuda_bf16.h>
#include <cstdint>

// FourierCrossAttention: B=64, L=S=2048, H=8, E=64, MODES=64, O=64
// out[b,h,o,l] = irfft_l( scatter( w-contraction( tanh(Xq^T Xk) Xk ) ) ) / (512*512)

#define N_B   64
#define N_L   2048
#define N_H   8
#define N_E   64
#define N_M   64
#define N_HE  512
#define N_J   128   // 2*N_M, interleaved (re,im)

typedef unsigned long long ull;

// ---------- scratch (static device globals; no runtime alloc) ----------------
__device__ double2 g_twd[N_L];             // twiddle table cos,sin (double)
__device__ float g_Bf[N_L * N_J];          // forward basis [l][j]
__device__ float g_Bi[N_J * N_L];          // inverse basis [j][l] (coef folded)
__device__ float g_Xq[N_B * N_HE * N_J];
__device__ float g_Xk[N_B * N_HE * N_J];
__device__ float g_Spec[N_B * N_HE * N_J];

// ---------- packed f32x2 helpers ---------------------------------------------
__device__ __forceinline__ ull pk2(float lo, float hi) {
    ull r; asm("mov.b64 %0, {%1, %2};" : "=l"(r) : "f"(lo), "f"(hi)); return r;
}
__device__ __forceinline__ void fma2(ull &d, ull a, ull b) {
    asm("fma.rn.f32x2 %0, %1, %2, %0;" : "+l"(d) : "l"(a), "l"(b));
}
__device__ __forceinline__ void add2(ull &d, ull a) {
    asm("add.rn.f32x2 %0, %0, %1;" : "+l"(d) : "l"(a));
}

// ---------- K-1: twiddle table (only 2048 double sincos on the whole chip) ---
__global__ void k_tw() {
    int i = blockIdx.x * blockDim.x + threadIdx.x;   // 2048 threads
    double s, c;
    sincos((double)i * (6.283185307179586476925287 / 2048.0), &s, &c);
    g_twd[i] = make_double2(c, s);
}

// ---------- K0: basis tables (gather from table; no heavy math) --------------
__global__ void k_basis() {
    int idx = blockIdx.x * blockDim.x + threadIdx.x;   // 64*2048 threads
    int m = idx >> 11;
    int l = idx & 2047;
    double2 t = g_twd[(m * l) & 2047];
    g_Bf[l * N_J + 2 * m]     = (float)t.x;
    g_Bf[l * N_J + 2 * m + 1] = (float)(-t.y);
    double coef = (m == 0 ? 1.0 : 2.0) / (2048.0 * 512.0 * 512.0);
    g_Bi[(2 * m) * N_L + l]     = (float)(coef * t.x);
    g_Bi[(2 * m + 1) * N_L + l] = (m == 0) ? 0.0f : (float)(-coef * t.y);
}

// ---------- K1: truncated DFT as GEMM, K=2048  (R6-proven layout) ------------
// grid (4 he-tiles, 64 b, 2 {q,k}); 128 thr; block tile 128he x 64 pairs (all j)
// thread tile: 8 he x 8 pairs (stride-8 pair assignment -> conflict-free LDS.64)
__global__ void __launch_bounds__(128) k_dft(const float* __restrict__ qp,
                                             const float* __restrict__ kp) {
    const float* src = blockIdx.z ? kp : qp;
    float* dst       = blockIdx.z ? g_Xk : g_Xq;
    int b = blockIdx.y;
    int he0 = blockIdx.x * 128;

    __shared__ __align__(16) float sA[32][128];   // [l][he]
    __shared__ __align__(16) float sB[32][128];   // [l][j]

    int t = threadIdx.x;
    int w = t >> 5, lane = t & 31;
    int tr = t >> 3, tc = t & 7;        // 16 x 8 thread grid
    int hs = tr * 8;                    // 8 he rows

    ull acc[8][8], accM[8][8];
#pragma unroll
    for (int i = 0; i < 8; i++)
#pragma unroll
        for (int q = 0; q < 8; q++) { acc[i][q] = 0ull; accM[i][q] = 0ull; }

    const float* abase = src + (size_t)b * N_L * N_HE + he0;

    for (int l0 = 0; l0 < N_L; l0 += 32) {
        // fill: each warp fills rows w, w+4, ..., w+28 ; one full row per step
#pragma unroll
        for (int rr = 0; rr < 8; rr++) {
            int row = w + rr * 4;
            *(float4*)&sA[row][lane * 4] =
                *(const float4*)(abase + (size_t)(l0 + row) * N_HE + lane * 4);
            *(float4*)&sB[row][lane * 4] =
                *(const float4*)(g_Bf + (size_t)(l0 + row) * N_J + lane * 4);
        }
        __syncthreads();
#pragma unroll 4
        for (int kk = 0; kk < 32; kk++) {
            float4 a0 = *(float4*)&sA[kk][hs];
            float4 a1 = *(float4*)&sA[kk][hs + 4];
            ull aa[8];
            aa[0] = pk2(a0.x, a0.x); aa[1] = pk2(a0.y, a0.y);
            aa[2] = pk2(a0.z, a0.z); aa[3] = pk2(a0.w, a0.w);
            aa[4] = pk2(a1.x, a1.x); aa[5] = pk2(a1.y, a1.y);
            aa[6] = pk2(a1.z, a1.z); aa[7] = pk2(a1.w, a1.w);
            ull bb[8];
#pragma unroll
            for (int i = 0; i < 8; i++)
                bb[i] = *(ull*)&sB[kk][2 * (tc + 8 * i)];
#pragma unroll
            for (int hi = 0; hi < 8; hi++)
#pragma unroll
                for (int i = 0; i < 8; i++)
                    fma2(acc[hi][i], aa[hi], bb[i]);
        }
        __syncthreads();
        if (((l0 >> 5) & 7) == 7) {   // flush every 256 l's: tames fp32 drift
#pragma unroll
            for (int i = 0; i < 8; i++)
#pragma unroll
                for (int q = 0; q < 8; q++) { add2(accM[i][q], acc[i][q]); acc[i][q] = 0ull; }
        }
    }
#pragma unroll
    for (int hi = 0; hi < 8; hi++) {
        float* dp = dst + (size_t)(b * N_HE + he0 + hs + hi) * N_J;
#pragma unroll
        for (int i = 0; i < 8; i++)
            *(ull*)&dp[2 * (tc + 8 * i)] = accM[hi][i];
    }
}

// ---------- complex tanh: fast saturated path + stable double fallback -------
__device__ __forceinline__ float2 ctanh_c(float re, float im) {
    if (fabsf(re) > 9.5f)                      // |tanh|=1 to fp32; im ~ 2e^-19
        return make_float2(re > 0.0f ? 1.0f : -1.0f, 0.0f);
    double tx = tanh((double)re);
    double ty = tan((double)im);
    double tx2 = tx * tx, ty2 = ty * ty;
    double inv = 1.0 / (1.0 + tx2 * ty2);
    return make_float2((float)(tx * (1.0 + ty2) * inv),
                       (float)(ty * (1.0 - tx2) * inv));
}

// ---------- K2: fused middle stage, one block per (b,h) ----------------------
#define K2_SMEM (3 * 64 * 66 * (int)sizeof(float2))
__global__ void __launch_bounds__(256, 2) k_mid(const float* __restrict__ w1r,
                                                const float* __restrict__ w1i) {
    int bh = blockIdx.x;
    int b = bh >> 3, h = bh & 7;
    extern __shared__ float2 sm2[];
    float2 (*sQ)[66] = (float2(*)[66])sm2;          // Xq[e][x] -> later Xqkv
    float2 (*sK)[66] = ((float2(*)[66])sm2) + 64;   // Xk[e][y]
    float2 (*sA)[66] = ((float2(*)[66])sm2) + 128;  // A[y][x]

    int t = threadIdx.x;
    int r = t >> 4, c = t & 15;
    int xs = c * 4;

    const float* xqb = g_Xq + (size_t)(b * N_HE + h * N_E) * N_J;
    const float* xkb = g_Xk + (size_t)(b * N_HE + h * N_E) * N_J;
    for (int i = t; i < 64 * 32; i += 256) {
        int row = i >> 5, c4 = i & 31;
        *(float4*)&sQ[row][c4 * 2] = *(const float4*)(xqb + row * N_J + c4 * 4);
        *(float4*)&sK[row][c4 * 2] = *(const float4*)(xkb + row * N_J + c4 * 4);
    }
    __syncthreads();

    // stage A: A[x][y] = tanh( sum_e Xq[e][x]*Xk[e][y] )   (no conjugate)
    {
        int ys = r * 4;
        float are[4][4] = {}, aim[4][4] = {};
        for (int e = 0; e < 64; e++) {
            float4 q0 = *(float4*)&sQ[e][xs];
            float4 q1 = *(float4*)&sQ[e][xs + 2];
            float qr[4] = {q0.x, q0.z, q1.x, q1.z};
            float qi[4] = {q0.y, q0.w, q1.y, q1.w};
            float4 k0 = *(float4*)&sK[e][ys];
            float4 k1 = *(float4*)&sK[e][ys + 2];
            float kr[4] = {k0.x, k0.z, k1.x, k1.z};
            float ki[4] = {k0.y, k0.w, k1.y, k1.w};
#pragma unroll
            for (int i = 0; i < 4; i++)
#pragma unroll
                for (int j = 0; j < 4; j++) {
                    are[i][j] = fmaf(qr[i], kr[j], are[i][j]);
                    are[i][j] = fmaf(-qi[i], ki[j], are[i][j]);
                    aim[i][j] = fmaf(qr[i], ki[j], aim[i][j]);
                    aim[i][j] = fmaf(qi[i], kr[j], aim[i][j]);
                }
        }
#pragma unroll
        for (int i = 0; i < 4; i++)
#pragma unroll
            for (int j = 0; j < 4; j++)
                sA[ys + j][xs + i] = ctanh_c(are[i][j], aim[i][j]);
    }
    __syncthreads();

    // stage B: Xqkv[e][x] = sum_y A[x][y]*Xk[e][y]   -> overwrite sQ
    {
        int es = r * 4;
        float vre[4][4] = {}, vim[4][4] = {};   // [e][x]
        for (int y = 0; y < 64; y++) {
            float4 a0 = *(float4*)&sA[y][xs];
            float4 a1 = *(float4*)&sA[y][xs + 2];
            float ar[4] = {a0.x, a0.z, a1.x, a1.z};
            float ai[4] = {a0.y, a0.w, a1.y, a1.w};
            float2 kv[4];
#pragma unroll
            for (int j = 0; j < 4; j++) kv[j] = sK[es + j][y];
#pragma unroll
            for (int ei = 0; ei < 4; ei++)
#pragma unroll
                for (int xi = 0; xi < 4; xi++) {
                    vre[ei][xi] = fmaf(ar[xi], kv[ei].x, vre[ei][xi]);
                    vre[ei][xi] = fmaf(-ai[xi], kv[ei].y, vre[ei][xi]);
                    vim[ei][xi] = fmaf(ar[xi], kv[ei].y, vim[ei][xi]);
                    vim[ei][xi] = fmaf(ai[xi], kv[ei].x, vim[ei][xi]);
                }
        }
        __syncthreads();
#pragma unroll
        for (int ei = 0; ei < 4; ei++)
#pragma unroll
            for (int xi = 0; xi < 4; xi++)
                sQ[es + ei][xs + xi] = make_float2(vre[ei][xi], vim[ei][xi]);
    }
    __syncthreads();

    // stage C: Spec[o][x] = sum_e Xqkv[e][x] * w[h,e,o,x]
    {
        int os = r * 4;
        float sre[4][4] = {}, sim_[4][4] = {};  // [o][x]
        for (int e = 0; e < 64; e++) {
            float4 x0 = *(float4*)&sQ[e][xs];
            float4 x1 = *(float4*)&sQ[e][xs + 2];
            float xr[4] = {x0.x, x0.z, x1.x, x1.z};
            float xi_[4] = {x0.y, x0.w, x1.y, x1.w};
            size_t wo = (((size_t)h * 64 + e) * 64 + os) * 64 + xs;
#pragma unroll
            for (int j = 0; j < 4; j++) {
                float4 w4r = *(const float4*)(w1r + wo + (size_t)j * 64);
                float4 w4i = *(const float4*)(w1i + wo + (size_t)j * 64);
                float wr[4] = {w4r.x, w4r.y, w4r.z, w4r.w};
                float wi[4] = {w4i.x, w4i.y, w4i.z, w4i.w};
#pragma unroll
                for (int i = 0; i < 4; i++) {
                    sre[j][i]  = fmaf(xr[i],  wr[i], sre[j][i]);
                    sre[j][i]  = fmaf(-xi_[i], wi[i], sre[j][i]);
                    sim_[j][i] = fmaf(xr[i],  wi[i], sim_[j][i]);
                    sim_[j][i] = fmaf(xi_[i], wr[i], sim_[j][i]);
                }
            }
        }
        float* sp = g_Spec + (size_t)(b * N_HE + h * N_E) * N_J;
#pragma unroll
        for (int j = 0; j < 4; j++)
#pragma unroll
            for (int i = 0; i < 4; i++)
                *(float2*)&sp[(os + j) * N_J + 2 * (xs + i)] =
                    make_float2(sre[j][i], sim_[j][i]);
    }
}

// ---------- K3: irfft as GEMM, K=128  (R6-proven layout) ---------------------
// grid (16 l-tiles, 256 row-tiles); 128 thr; block tile 128 rows x 128 l
// thread tile: 8 rows x 8 l-pairs (stride-8). Spec held transposed in smem.
__global__ void __launch_bounds__(128) k_irfft(float* __restrict__ out) {
    int l0 = blockIdx.x * 128;
    int r0 = blockIdx.y * 128;

    __shared__ __align__(16) float sST[32][128];   // [j][row]  (transposed)
    __shared__ __align__(16) float sB[32][128];    // [j][l]

    int t = threadIdx.x;
    int w = t >> 5, lane = t & 31;
    int tr = t >> 3, tc = t & 7;
    int hs = tr * 8;

    ull acc[8][8];
#pragma unroll
    for (int i = 0; i < 8; i++)
#pragma unroll
        for (int q = 0; q < 8; q++) acc[i][q] = 0ull;

    for (int j0 = 0; j0 < N_J; j0 += 32) {
        // Spec transpose fill: thread t owns Spec row r0+t; STS.32 bank = t%32 (clean)
        {
            const float* gs = g_Spec + (size_t)(r0 + t) * N_J + j0;
#pragma unroll
            for (int u = 0; u < 8; u++) {
                float4 v = *(const float4*)(gs + u * 4);
                sST[u * 4 + 0][t] = v.x;
                sST[u * 4 + 1][t] = v.y;
                sST[u * 4 + 2][t] = v.z;
                sST[u * 4 + 3][t] = v.w;
            }
        }
        // Bi fill: warp-per-row, coalesced
#pragma unroll
        for (int rr = 0; rr < 8; rr++) {
            int row = w + rr * 4;
            *(float4*)&sB[row][lane * 4] =
                *(const float4*)(g_Bi + (size_t)(j0 + row) * N_L + l0 + lane * 4);
        }
        __syncthreads();
#pragma unroll 4
        for (int kk = 0; kk < 32; kk++) {
            float4 a0 = *(float4*)&sST[kk][hs];
            float4 a1 = *(float4*)&sST[kk][hs + 4];
            ull aa[8];
            aa[0] = pk2(a0.x, a0.x); aa[1] = pk2(a0.y, a0.y);
            aa[2] = pk2(a0.z, a0.z); aa[3] = pk2(a0.w, a0.w);
            aa[4] = pk2(a1.x, a1.x); aa[5] = pk2(a1.y, a1.y);
            aa[6] = pk2(a1.z, a1.z); aa[7] = pk2(a1.w, a1.w);
            ull bb[8];
#pragma unroll
            for (int i = 0; i < 8; i++)
                bb[i] = *(ull*)&sB[kk][2 * (tc + 8 * i)];
#pragma unroll
            for (int hi = 0; hi < 8; hi++)
#pragma unroll
                for (int i = 0; i < 8; i++)
                    fma2(acc[hi][i], aa[hi], bb[i]);
        }
        __syncthreads();
    }
#pragma unroll
    for (int hi = 0; hi < 8; hi++) {
        float* dp = out + (size_t)(r0 + hs + hi) * N_L + l0;
#pragma unroll
        for (int i = 0; i < 8; i++)
            *(ull*)&dp[2 * (tc + 8 * i)] = acc[hi][i];
    }
}

// ---------- launch ------------------------------------------------------------
extern "C" void kernel_launch(void* const* d_in, const int* in_sizes, int n_in,
                              void* d_out, int out_size) {
    const float* q   = (const float*)d_in[0];
    const float* k   = (const float*)d_in[1];
    const float* w1r = (const float*)d_in[3];
    const float* w1i = (const float*)d_in[4];
    float* out = (float*)d_out;

    cudaFuncSetAttribute(k_mid, cudaFuncAttributeMaxDynamicSharedMemorySize, K2_SMEM);

    k_tw<<<8, 256>>>();
    k_basis<<<512, 256>>>();
    dim3 g1(4, 64, 2);
    k_dft<<<g1, 128>>>(q, k);
    k_mid<<<512, 256, K2_SMEM>>>(w1r, w1i);
    dim3 g3(16, 256);
    k_irfft<<<g3, 128>>>(out);
}

// round 10
// speedup vs baseline: 2.2798x; 1.2404x over previous
#include <cuda_runtime.h>
#include <cuda_bf16.h>
#include <cstdint>

// FourierCrossAttention: B=64, L=S=2048, H=8, E=64, MODES=64, O=64
// Folded (conjugate-symmetric) DFT + irfft: half the FLOPs of the naive GEMMs.

#define N_B   64
#define N_L   2048
#define N_H   8
#define N_E   64
#define N_M   64
#define N_HE  512
#define N_J   128   // 2*N_M, interleaved (re,im)
#define BIP_W 1056  // padded row width of g_Bip (l = 0..1024 used)

typedef unsigned long long ull;

// ---------- scratch (static device globals; no runtime alloc) ----------------
__device__ double2 g_twd[N_L];             // twiddle table cos,sin (double)
__device__ float  g_Bf[N_L * N_J];         // forward basis [l][j]=(cos,-sin)
__device__ float2 g_Bip[N_M * BIP_W];      // inverse basis [m][l]=(coef*cos, coef*sin)
__device__ float g_Xq[N_B * N_HE * N_J];
__device__ float g_Xk[N_B * N_HE * N_J];
__device__ float g_Spec[N_B * N_HE * N_J];

// ---------- packed f32x2 helpers ---------------------------------------------
__device__ __forceinline__ ull pk2(float lo, float hi) {
    ull r; asm("mov.b64 %0, {%1, %2};" : "=l"(r) : "f"(lo), "f"(hi)); return r;
}
__device__ __forceinline__ void upk2(float &lo, float &hi, ull v) {
    asm("mov.b64 {%0, %1}, %2;" : "=f"(lo), "=f"(hi) : "l"(v));
}
__device__ __forceinline__ void fma2(ull &d, ull a, ull b) {
    asm("fma.rn.f32x2 %0, %1, %2, %0;" : "+l"(d) : "l"(a), "l"(b));
}
__device__ __forceinline__ void add2(ull &d, ull a) {
    asm("add.rn.f32x2 %0, %0, %1;" : "+l"(d) : "l"(a));
}

// ---------- K-1: twiddle table (only 2048 double sincos on the whole chip) ---
__global__ void k_tw() {
    int i = blockIdx.x * blockDim.x + threadIdx.x;   // 2048 threads
    double s, c;
    sincos((double)i * (6.283185307179586476925287 / 2048.0), &s, &c);
    g_twd[i] = make_double2(c, s);
}

// ---------- K0: basis tables (gather from table; no heavy math) --------------
__global__ void k_basis() {
    int idx = blockIdx.x * blockDim.x + threadIdx.x;   // 64*2048 threads
    int m = idx >> 11;
    int l = idx & 2047;
    double2 t = g_twd[(m * l) & 2047];
    g_Bf[l * N_J + 2 * m]     = (float)t.x;
    g_Bf[l * N_J + 2 * m + 1] = (float)(-t.y);
    if (l < BIP_W) {
        double coef = (m == 0 ? 1.0 : 2.0) / (2048.0 * 512.0 * 512.0);
        float2 v = (l <= 1024)
                 ? make_float2((float)(coef * t.x), (float)(coef * t.y))
                 : make_float2(0.0f, 0.0f);
        g_Bip[m * BIP_W + l] = v;
    }
}

// ---------- K1: folded truncated DFT as GEMM, K=1024 -------------------------
// X_m = x[0] + sum_{l=1}^{1024} (Fp[l]*cos - i*Fm[l]*sin),
//   Fp = x[l]+x[2048-l], Fm = x[l]-x[2048-l]  (l=1024: Fp=x, Fm=0).
// grid (4 he-tiles, 64 b, 2 {q,k}); 128 thr; thread tile 8he x 8 mode-pairs.
__global__ void __launch_bounds__(128) k_dft(const float* __restrict__ qp,
                                             const float* __restrict__ kp) {
    const float* src = blockIdx.z ? kp : qp;
    float* dst       = blockIdx.z ? g_Xk : g_Xq;
    int b = blockIdx.y;
    int he0 = blockIdx.x * 128;

    __shared__ __align__(16) float sAp[32][128];  // [l][he] folded sum
    __shared__ __align__(16) float sAm[32][128];  // [l][he] folded diff
    __shared__ __align__(16) float sB[32][128];   // [l][j]
    __shared__ __align__(16) float sA0[128];      // x[0] slice

    int t = threadIdx.x;
    int w = t >> 5, lane = t & 31;
    int tr = t >> 3, tc = t & 7;
    int hs = tr * 8;

    ull acc[8][8], accM[8][8];
#pragma unroll
    for (int i = 0; i < 8; i++)
#pragma unroll
        for (int q = 0; q < 8; q++) { acc[i][q] = 0ull; accM[i][q] = 0ull; }

    const float* abase = src + (size_t)b * N_L * N_HE + he0;

    if (t < 32)
        *(float4*)&sA0[t * 4] = *(const float4*)(abase + t * 4);

    for (int tile = 0; tile < 32; tile++) {
        int lbase = 1 + tile * 32;
        // fill: each warp fills rows w, w+4, ..., w+28
#pragma unroll
        for (int rr = 0; rr < 8; rr++) {
            int row = w + rr * 4;
            int l = lbase + row;
            float4 xl = *(const float4*)(abase + (size_t)l * N_HE + lane * 4);
            float4 xr = *(const float4*)(abase + (size_t)(2048 - l) * N_HE + lane * 4);
            float4 fp, fm;
            if (l == 1024) {
                fp = xl; fm = make_float4(0.f, 0.f, 0.f, 0.f);
            } else {
                fp = make_float4(xl.x + xr.x, xl.y + xr.y, xl.z + xr.z, xl.w + xr.w);
                fm = make_float4(xl.x - xr.x, xl.y - xr.y, xl.z - xr.z, xl.w - xr.w);
            }
            *(float4*)&sAp[row][lane * 4] = fp;
            *(float4*)&sAm[row][lane * 4] = fm;
            *(float4*)&sB[row][lane * 4] =
                *(const float4*)(g_Bf + (size_t)l * N_J + lane * 4);
        }
        __syncthreads();
#pragma unroll 4
        for (int kk = 0; kk < 32; kk++) {
            float4 p0 = *(float4*)&sAp[kk][hs];
            float4 p1 = *(float4*)&sAp[kk][hs + 4];
            float4 m0 = *(float4*)&sAm[kk][hs];
            float4 m1 = *(float4*)&sAm[kk][hs + 4];
            ull aa[8];
            aa[0] = pk2(p0.x, m0.x); aa[1] = pk2(p0.y, m0.y);
            aa[2] = pk2(p0.z, m0.z); aa[3] = pk2(p0.w, m0.w);
            aa[4] = pk2(p1.x, m1.x); aa[5] = pk2(p1.y, m1.y);
            aa[6] = pk2(p1.z, m1.z); aa[7] = pk2(p1.w, m1.w);
            ull bb[8];
#pragma unroll
            for (int i = 0; i < 8; i++)
                bb[i] = *(ull*)&sB[kk][2 * (tc + 8 * i)];
#pragma unroll
            for (int hi = 0; hi < 8; hi++)
#pragma unroll
                for (int i = 0; i < 8; i++)
                    fma2(acc[hi][i], aa[hi], bb[i]);
        }
        __syncthreads();
        if ((tile & 7) == 7) {   // flush every 256 l's: tames fp32 drift
#pragma unroll
            for (int i = 0; i < 8; i++)
#pragma unroll
                for (int q = 0; q < 8; q++) { add2(accM[i][q], acc[i][q]); acc[i][q] = 0ull; }
        }
    }
    // l = 0 term: Re += x[0] for every mode
#pragma unroll
    for (int hi = 0; hi < 8; hi++) {
        ull e = pk2(sA0[hs + hi], 0.0f);
#pragma unroll
        for (int i = 0; i < 8; i++) add2(accM[hi][i], e);
    }
#pragma unroll
    for (int hi = 0; hi < 8; hi++) {
        float* dp = dst + (size_t)(b * N_HE + he0 + hs + hi) * N_J;
#pragma unroll
        for (int i = 0; i < 8; i++)
            *(ull*)&dp[2 * (tc + 8 * i)] = accM[hi][i];
    }
}

// ---------- complex tanh: fast saturated path + stable double fallback -------
__device__ __forceinline__ float2 ctanh_c(float re, float im) {
    if (fabsf(re) > 9.5f)                      // |tanh|=1 to fp32
        return make_float2(re > 0.0f ? 1.0f : -1.0f, 0.0f);
    double tx = tanh((double)re);
    double ty = tan((double)im);
    double tx2 = tx * tx, ty2 = ty * ty;
    double inv = 1.0 / (1.0 + tx2 * ty2);
    return make_float2((float)(tx * (1.0 + ty2) * inv),
                       (float)(ty * (1.0 - tx2) * inv));
}

// ---------- K2: fused middle stage, one block per (b,h) ----------------------
#define K2_SMEM (3 * 64 * 66 * (int)sizeof(float2))
__global__ void __launch_bounds__(256, 2) k_mid(const float* __restrict__ w1r,
                                                const float* __restrict__ w1i) {
    int bh = blockIdx.x;
    int b = bh >> 3, h = bh & 7;
    extern __shared__ float2 sm2[];
    float2 (*sQ)[66] = (float2(*)[66])sm2;          // Xq[e][x] -> later Xqkv
    float2 (*sK)[66] = ((float2(*)[66])sm2) + 64;   // Xk[e][y]
    float2 (*sA)[66] = ((float2(*)[66])sm2) + 128;  // A[y][x]

    int t = threadIdx.x;
    int r = t >> 4, c = t & 15;
    int xs = c * 4;

    const float* xqb = g_Xq + (size_t)(b * N_HE + h * N_E) * N_J;
    const float* xkb = g_Xk + (size_t)(b * N_HE + h * N_E) * N_J;
    for (int i = t; i < 64 * 32; i += 256) {
        int row = i >> 5, c4 = i & 31;
        *(float4*)&sQ[row][c4 * 2] = *(const float4*)(xqb + row * N_J + c4 * 4);
        *(float4*)&sK[row][c4 * 2] = *(const float4*)(xkb + row * N_J + c4 * 4);
    }
    __syncthreads();

    // stage A: A[x][y] = tanh( sum_e Xq[e][x]*Xk[e][y] )   (no conjugate)
    {
        int ys = r * 4;
        float are[4][4] = {}, aim[4][4] = {};
        for (int e = 0; e < 64; e++) {
            float4 q0 = *(float4*)&sQ[e][xs];
            float4 q1 = *(float4*)&sQ[e][xs + 2];
            float qr[4] = {q0.x, q0.z, q1.x, q1.z};
            float qi[4] = {q0.y, q0.w, q1.y, q1.w};
            float4 k0 = *(float4*)&sK[e][ys];
            float4 k1 = *(float4*)&sK[e][ys + 2];
            float kr[4] = {k0.x, k0.z, k1.x, k1.z};
            float ki[4] = {k0.y, k0.w, k1.y, k1.w};
#pragma unroll
            for (int i = 0; i < 4; i++)
#pragma unroll
                for (int j = 0; j < 4; j++) {
                    are[i][j] = fmaf(qr[i], kr[j], are[i][j]);
                    are[i][j] = fmaf(-qi[i], ki[j], are[i][j]);
                    aim[i][j] = fmaf(qr[i], ki[j], aim[i][j]);
                    aim[i][j] = fmaf(qi[i], kr[j], aim[i][j]);
                }
        }
#pragma unroll
        for (int i = 0; i < 4; i++)
#pragma unroll
            for (int j = 0; j < 4; j++)
                sA[ys + j][xs + i] = ctanh_c(are[i][j], aim[i][j]);
    }
    __syncthreads();

    // stage B: Xqkv[e][x] = sum_y A[x][y]*Xk[e][y]   -> overwrite sQ
    {
        int es = r * 4;
        float vre[4][4] = {}, vim[4][4] = {};   // [e][x]
        for (int y = 0; y < 64; y++) {
            float4 a0 = *(float4*)&sA[y][xs];
            float4 a1 = *(float4*)&sA[y][xs + 2];
            float ar[4] = {a0.x, a0.z, a1.x, a1.z};
            float ai[4] = {a0.y, a0.w, a1.y, a1.w};
            float2 kv[4];
#pragma unroll
            for (int j = 0; j < 4; j++) kv[j] = sK[es + j][y];
#pragma unroll
            for (int ei = 0; ei < 4; ei++)
#pragma unroll
                for (int xi = 0; xi < 4; xi++) {
                    vre[ei][xi] = fmaf(ar[xi], kv[ei].x, vre[ei][xi]);
                    vre[ei][xi] = fmaf(-ai[xi], kv[ei].y, vre[ei][xi]);
                    vim[ei][xi] = fmaf(ar[xi], kv[ei].y, vim[ei][xi]);
                    vim[ei][xi] = fmaf(ai[xi], kv[ei].x, vim[ei][xi]);
                }
        }
        __syncthreads();
#pragma unroll
        for (int ei = 0; ei < 4; ei++)
#pragma unroll
            for (int xi = 0; xi < 4; xi++)
                sQ[es + ei][xs + xi] = make_float2(vre[ei][xi], vim[ei][xi]);
    }
    __syncthreads();

    // stage C: Spec[o][x] = sum_e Xqkv[e][x] * w[h,e,o,x]
    {
        int os = r * 4;
        float sre[4][4] = {}, sim_[4][4] = {};  // [o][x]
        for (int e = 0; e < 64; e++) {
            float4 x0 = *(float4*)&sQ[e][xs];
            float4 x1 = *(float4*)&sQ[e][xs + 2];
            float xr[4] = {x0.x, x0.z, x1.x, x1.z};
            float xi_[4] = {x0.y, x0.w, x1.y, x1.w};
            size_t wo = (((size_t)h * 64 + e) * 64 + os) * 64 + xs;
#pragma unroll
            for (int j = 0; j < 4; j++) {
                float4 w4r = *(const float4*)(w1r + wo + (size_t)j * 64);
                float4 w4i = *(const float4*)(w1i + wo + (size_t)j * 64);
                float wr[4] = {w4r.x, w4r.y, w4r.z, w4r.w};
                float wi[4] = {w4i.x, w4i.y, w4i.z, w4i.w};
#pragma unroll
                for (int i = 0; i < 4; i++) {
                    sre[j][i]  = fmaf(xr[i],  wr[i], sre[j][i]);
                    sre[j][i]  = fmaf(-xi_[i], wi[i], sre[j][i]);
                    sim_[j][i] = fmaf(xr[i],  wi[i], sim_[j][i]);
                    sim_[j][i] = fmaf(xi_[i], wr[i], sim_[j][i]);
                }
            }
        }
        float* sp = g_Spec + (size_t)(b * N_HE + h * N_E) * N_J;
#pragma unroll
        for (int j = 0; j < 4; j++)
#pragma unroll
            for (int i = 0; i < 4; i++)
                *(float2*)&sp[(os + j) * N_J + 2 * (xs + i)] =
                    make_float2(sre[j][i], sim_[j][i]);
    }
}

// ---------- K3: folded irfft, K=64 modes, outputs l=0..1023 + mirrors --------
// acc lanes carry (C,S); out[l]=C-S, out[2048-l]=C+S.
// grid (16 l-tiles of 64, 256 row-tiles); 128 thr; thread tile 8 rows x 8 l.
__global__ void __launch_bounds__(128) k_irfft(float* __restrict__ out) {
    int l0 = blockIdx.x * 64;
    int r0 = blockIdx.y * 128;

    __shared__ __align__(16) ull sSp[16][128];  // (Re,Im) [mode][row]
    __shared__ __align__(16) ull sBp[16][64];   // (coef*cos, coef*sin) [mode][l]

    int t = threadIdx.x;
    int w = t >> 5, lane = t & 31;
    int tr = t >> 3, tc = t & 7;
    int hs = tr * 8;

    ull acc[8][8];
#pragma unroll
    for (int i = 0; i < 8; i++)
#pragma unroll
        for (int q = 0; q < 8; q++) acc[i][q] = 0ull;

    for (int m0 = 0; m0 < 64; m0 += 16) {
        // Spec fill: thread t owns row r0+t; 8 x LDG.128 covering 16 modes
        {
            const float* gs = g_Spec + (size_t)(r0 + t) * N_J + 2 * m0;
#pragma unroll
            for (int u = 0; u < 8; u++) {
                float4 v = *(const float4*)(gs + u * 4);
                sSp[2 * u][t]     = ((ull*)&v)[0];
                sSp[2 * u + 1][t] = ((ull*)&v)[1];
            }
        }
        // B fill: warp w fills rows 4w..4w+3; each lane 1 ulonglong2 (2 pairs)
#pragma unroll
        for (int rr = 0; rr < 4; rr++) {
            int mm = w * 4 + rr;
            const float2* gb = g_Bip + (size_t)(m0 + mm) * BIP_W + l0 + lane * 2;
            *(ulonglong2*)&sBp[mm][lane * 2] = *(const ulonglong2*)gb;
        }
        __syncthreads();
#pragma unroll 4
        for (int kk = 0; kk < 16; kk++) {
            ull aa[8];
#pragma unroll
            for (int hi = 0; hi < 8; hi++) aa[hi] = sSp[kk][hs + hi];
            ull bb[8];
#pragma unroll
            for (int i = 0; i < 8; i++) bb[i] = sBp[kk][tc + 8 * i];
#pragma unroll
            for (int hi = 0; hi < 8; hi++)
#pragma unroll
                for (int i = 0; i < 8; i++)
                    fma2(acc[hi][i], aa[hi], bb[i]);
        }
        __syncthreads();
    }
#pragma unroll
    for (int hi = 0; hi < 8; hi++) {
        float* op = out + (size_t)(r0 + hs + hi) * N_L;
#pragma unroll
        for (int i = 0; i < 8; i++) {
            int l = l0 + tc + 8 * i;
            float cC, cS;
            upk2(cC, cS, acc[hi][i]);
            op[l] = cC - cS;
            if (l) op[2048 - l] = cC + cS;
        }
    }
}

// ---------- K4: column l=1024 (sin term vanishes) ----------------------------
__global__ void k_edge(float* __restrict__ out) {
    int row = blockIdx.x * blockDim.x + threadIdx.x;   // 32768 rows
    const float* sp = g_Spec + (size_t)row * N_J;
    float s = 0.0f;
#pragma unroll
    for (int m = 0; m < 64; m++)
        s = fmaf(sp[2 * m], g_Bip[m * BIP_W + 1024].x, s);
    out[(size_t)row * N_L + 1024] = s;
}

// ---------- launch ------------------------------------------------------------
extern "C" void kernel_launch(void* const* d_in, const int* in_sizes, int n_in,
                              void* d_out, int out_size) {
    const float* q   = (const float*)d_in[0];
    const float* k   = (const float*)d_in[1];
    const float* w1r = (const float*)d_in[3];
    const float* w1i = (const float*)d_in[4];
    float* out = (float*)d_out;

    cudaFuncSetAttribute(k_mid, cudaFuncAttributeMaxDynamicSharedMemorySize, K2_SMEM);

    k_tw<<<8, 256>>>();
    k_basis<<<512, 256>>>();
    dim3 g1(4, 64, 2);
    k_dft<<<g1, 128>>>(q, k);
    k_mid<<<512, 256, K2_SMEM>>>(w1r, w1i);
    dim3 g3(16, 256);
    k_irfft<<<g3, 128>>>(out);
    k_edge<<<128, 256>>>(out);
}

// round 11
// speedup vs baseline: 3.5116x; 1.5403x over previous
#include <cuda_runtime.h>
#include <cuda_bf16.h>
#include <cstdint>

// FourierCrossAttention: B=64, L=S=2048, H=8, E=64, MODES=64, O=64
// Double-folded (radix-2 x2) DFT + irfft: 1/4 the FLOPs of the naive GEMMs.

#define N_B   64
#define N_L   2048
#define N_H   8
#define N_E   64
#define N_M   64
#define N_HE  512
#define N_J   128   // 2*N_M, interleaved (re,im)
#define BIP_W 1056  // padded row width of g_Bip (l = 0..1024 used)

typedef unsigned long long ull;

// ---------- scratch (static device globals; no runtime alloc) ----------------
__device__ double2 g_twd[N_L];             // twiddle table cos,sin (double)
__device__ float  g_Bf[N_L * N_J];         // forward basis [l][j]=(cos,-sin)
__device__ float2 g_Bip[N_M * BIP_W];      // inverse basis [m][l]=(coef*cos, coef*sin)
__device__ float g_Xq[N_B * N_HE * N_J];
__device__ float g_Xk[N_B * N_HE * N_J];
__device__ float g_Spec[N_B * N_HE * N_J];

// ---------- packed f32x2 helpers ---------------------------------------------
__device__ __forceinline__ ull pk2(float lo, float hi) {
    ull r; asm("mov.b64 %0, {%1, %2};" : "=l"(r) : "f"(lo), "f"(hi)); return r;
}
__device__ __forceinline__ void upk2(float &lo, float &hi, ull v) {
    asm("mov.b64 {%0, %1}, %2;" : "=f"(lo), "=f"(hi) : "l"(v));
}
__device__ __forceinline__ void fma2(ull &d, ull a, ull b) {
    asm("fma.rn.f32x2 %0, %1, %2, %0;" : "+l"(d) : "l"(a), "l"(b));
}
__device__ __forceinline__ void add2(ull &d, ull a) {
    asm("add.rn.f32x2 %0, %0, %1;" : "+l"(d) : "l"(a));
}

// ---------- K-1: twiddle table ------------------------------------------------
__global__ void k_tw() {
    int i = blockIdx.x * blockDim.x + threadIdx.x;   // 2048 threads
    double s, c;
    sincos((double)i * (6.283185307179586476925287 / 2048.0), &s, &c);
    g_twd[i] = make_double2(c, s);
}

// ---------- K0: basis tables (gather from table; no heavy math) --------------
__global__ void k_basis() {
    int idx = blockIdx.x * blockDim.x + threadIdx.x;   // 64*2048 threads
    int m = idx >> 11;
    int l = idx & 2047;
    double2 t = g_twd[(m * l) & 2047];
    g_Bf[l * N_J + 2 * m]     = (float)t.x;
    g_Bf[l * N_J + 2 * m + 1] = (float)(-t.y);
    if (l < BIP_W) {
        double coef = (m == 0 ? 1.0 : 2.0) / (2048.0 * 512.0 * 512.0);
        float2 v = (l <= 1024)
                 ? make_float2((float)(coef * t.x), (float)(coef * t.y))
                 : make_float2(0.0f, 0.0f);
        g_Bip[m * BIP_W + l] = v;
    }
}

// ---------- K1: double-folded DFT as GEMM, K=512 ------------------------------
// Pairs l & 2048-l (first fold -> Fp,Fm), then l & 1024-l (second fold, mode
// parity). Thread modes tc+8i share parity of tc -> select sGE or sGO plane.
// grid (4 he-tiles, 64 b, 2 {q,k}); 128 thr; thread tile 8he x 8 modes.
__global__ void __launch_bounds__(128) k_dft(const float* __restrict__ qp,
                                             const float* __restrict__ kp) {
    const float* src = blockIdx.z ? kp : qp;
    float* dst       = blockIdx.z ? g_Xk : g_Xq;
    int b = blockIdx.y;
    int he0 = blockIdx.x * 128;

    __shared__ __align__(16) ull  sGE[16][128];  // (Gpe,Gme) [l][he]
    __shared__ __align__(16) ull  sGO[16][128];  // (Gpo,Gmo) [l][he]
    __shared__ __align__(16) float sB[16][128];  // basis [l][j]
    __shared__ __align__(16) float sE[2][128];   // x[0], x[1024] slices

    int t = threadIdx.x;
    int w = t >> 5, lane = t & 31;
    int tr = t >> 3, tc = t & 7;
    int hs = tr * 8;

    ull acc[8][8];
#pragma unroll
    for (int i = 0; i < 8; i++)
#pragma unroll
        for (int q = 0; q < 8; q++) acc[i][q] = 0ull;

    const float* abase = src + (size_t)b * N_L * N_HE + he0;

    if (t < 32) {
        *(float4*)&sE[0][t * 4] = *(const float4*)(abase + t * 4);
        *(float4*)&sE[1][t * 4] =
            *(const float4*)(abase + (size_t)1024 * N_HE + t * 4);
    }

    const ull (*gsel)[128] = (tc & 1) ? sGO : sGE;

    for (int tile = 0; tile < 32; tile++) {
        int lbase = 1 + tile * 16;
        // fill: each warp fills rows w, w+4, w+8, w+12
#pragma unroll
        for (int rr = 0; rr < 4; rr++) {
            int row = w + rr * 4;
            int l = lbase + row;
            float4 xl = *(const float4*)(abase + (size_t)l * N_HE + lane * 4);
            float4 xr = *(const float4*)(abase + (size_t)(2048 - l) * N_HE + lane * 4);
            float4 xm = *(const float4*)(abase + (size_t)(1024 - l) * N_HE + lane * 4);
            float4 xp = *(const float4*)(abase + (size_t)(1024 + l) * N_HE + lane * 4);
            float h = (l == 512) ? 0.5f : 1.0f;
            const float* a = (const float*)&xl;
            const float* rmir = (const float*)&xr;
            const float* mmir = (const float*)&xm;
            const float* pmir = (const float*)&xp;
#pragma unroll
            for (int cc = 0; cc < 4; cc++) {
                float fp = a[cc] + rmir[cc];
                float fm = a[cc] - rmir[cc];
                float fq = mmir[cc] + pmir[cc];
                float fn = mmir[cc] - pmir[cc];
                sGE[row][lane * 4 + cc] = pk2(h * (fp + fq), h * (fm - fn));
                sGO[row][lane * 4 + cc] = pk2(h * (fp - fq), h * (fm + fn));
            }
            *(float4*)&sB[row][lane * 4] =
                *(const float4*)(g_Bf + (size_t)l * N_J + lane * 4);
        }
        __syncthreads();
#pragma unroll 4
        for (int kk = 0; kk < 16; kk++) {
            ull aa[8];
#pragma unroll
            for (int hi = 0; hi < 8; hi++) aa[hi] = gsel[kk][hs + hi];
            ull bb[8];
#pragma unroll
            for (int i = 0; i < 8; i++)
                bb[i] = *(ull*)&sB[kk][2 * (tc + 8 * i)];
#pragma unroll
            for (int hi = 0; hi < 8; hi++)
#pragma unroll
                for (int i = 0; i < 8; i++)
                    fma2(acc[hi][i], aa[hi], bb[i]);
        }
        __syncthreads();
    }
    // epilogue: l=0 adds x0 to Re (all m); l=1024 adds (-1)^m * x1024 to Re
    float sgn = (tc & 1) ? -1.0f : 1.0f;
#pragma unroll
    for (int hi = 0; hi < 8; hi++) {
        ull e = pk2(sE[0][hs + hi] + sgn * sE[1][hs + hi], 0.0f);
#pragma unroll
        for (int i = 0; i < 8; i++) add2(acc[hi][i], e);
    }
#pragma unroll
    for (int hi = 0; hi < 8; hi++) {
        float* dp = dst + (size_t)(b * N_HE + he0 + hs + hi) * N_J;
#pragma unroll
        for (int i = 0; i < 8; i++)
            *(ull*)&dp[2 * (tc + 8 * i)] = acc[hi][i];
    }
}

// ---------- complex tanh: fast saturated path + stable double fallback -------
__device__ __forceinline__ float2 ctanh_c(float re, float im) {
    if (fabsf(re) > 9.5f)
        return make_float2(re > 0.0f ? 1.0f : -1.0f, 0.0f);
    double tx = tanh((double)re);
    double ty = tan((double)im);
    double tx2 = tx * tx, ty2 = ty * ty;
    double inv = 1.0 / (1.0 + tx2 * ty2);
    return make_float2((float)(tx * (1.0 + ty2) * inv),
                       (float)(ty * (1.0 - tx2) * inv));
}

// ---------- K2: fused middle stage, one block per (b,h) ----------------------
#define K2_SMEM (3 * 64 * 66 * (int)sizeof(float2))
__global__ void __launch_bounds__(256, 2) k_mid(const float* __restrict__ w1r,
                                                const float* __restrict__ w1i) {
    int bh = blockIdx.x;
    int b = bh >> 3, h = bh & 7;
    extern __shared__ float2 sm2[];
    float2 (*sQ)[66] = (float2(*)[66])sm2;
    float2 (*sK)[66] = ((float2(*)[66])sm2) + 64;
    float2 (*sA)[66] = ((float2(*)[66])sm2) + 128;

    int t = threadIdx.x;
    int r = t >> 4, c = t & 15;
    int xs = c * 4;

    const float* xqb = g_Xq + (size_t)(b * N_HE + h * N_E) * N_J;
    const float* xkb = g_Xk + (size_t)(b * N_HE + h * N_E) * N_J;
    for (int i = t; i < 64 * 32; i += 256) {
        int row = i >> 5, c4 = i & 31;
        *(float4*)&sQ[row][c4 * 2] = *(const float4*)(xqb + row * N_J + c4 * 4);
        *(float4*)&sK[row][c4 * 2] = *(const float4*)(xkb + row * N_J + c4 * 4);
    }
    __syncthreads();

    // stage A: A[x][y] = tanh( sum_e Xq[e][x]*Xk[e][y] )
    {
        int ys = r * 4;
        float are[4][4] = {}, aim[4][4] = {};
        for (int e = 0; e < 64; e++) {
            float4 q0 = *(float4*)&sQ[e][xs];
            float4 q1 = *(float4*)&sQ[e][xs + 2];
            float qr[4] = {q0.x, q0.z, q1.x, q1.z};
            float qi[4] = {q0.y, q0.w, q1.y, q1.w};
            float4 k0 = *(float4*)&sK[e][ys];
            float4 k1 = *(float4*)&sK[e][ys + 2];
            float kr[4] = {k0.x, k0.z, k1.x, k1.z};
            float ki[4] = {k0.y, k0.w, k1.y, k1.w};
#pragma unroll
            for (int i = 0; i < 4; i++)
#pragma unroll
                for (int j = 0; j < 4; j++) {
                    are[i][j] = fmaf(qr[i], kr[j], are[i][j]);
                    are[i][j] = fmaf(-qi[i], ki[j], are[i][j]);
                    aim[i][j] = fmaf(qr[i], ki[j], aim[i][j]);
                    aim[i][j] = fmaf(qi[i], kr[j], aim[i][j]);
                }
        }
#pragma unroll
        for (int i = 0; i < 4; i++)
#pragma unroll
            for (int j = 0; j < 4; j++)
                sA[ys + j][xs + i] = ctanh_c(are[i][j], aim[i][j]);
    }
    __syncthreads();

    // stage B: Xqkv[e][x] = sum_y A[x][y]*Xk[e][y]   -> overwrite sQ
    {
        int es = r * 4;
        float vre[4][4] = {}, vim[4][4] = {};
        for (int y = 0; y < 64; y++) {
            float4 a0 = *(float4*)&sA[y][xs];
            float4 a1 = *(float4*)&sA[y][xs + 2];
            float ar[4] = {a0.x, a0.z, a1.x, a1.z};
            float ai[4] = {a0.y, a0.w, a1.y, a1.w};
            float2 kv[4];
#pragma unroll
            for (int j = 0; j < 4; j++) kv[j] = sK[es + j][y];
#pragma unroll
            for (int ei = 0; ei < 4; ei++)
#pragma unroll
                for (int xi = 0; xi < 4; xi++) {
                    vre[ei][xi] = fmaf(ar[xi], kv[ei].x, vre[ei][xi]);
                    vre[ei][xi] = fmaf(-ai[xi], kv[ei].y, vre[ei][xi]);
                    vim[ei][xi] = fmaf(ar[xi], kv[ei].y, vim[ei][xi]);
                    vim[ei][xi] = fmaf(ai[xi], kv[ei].x, vim[ei][xi]);
                }
        }
        __syncthreads();
#pragma unroll
        for (int ei = 0; ei < 4; ei++)
#pragma unroll
            for (int xi = 0; xi < 4; xi++)
                sQ[es + ei][xs + xi] = make_float2(vre[ei][xi], vim[ei][xi]);
    }
    __syncthreads();

    // stage C: Spec[o][x] = sum_e Xqkv[e][x] * w[h,e,o,x]
    {
        int os = r * 4;
        float sre[4][4] = {}, sim_[4][4] = {};
        for (int e = 0; e < 64; e++) {
            float4 x0 = *(float4*)&sQ[e][xs];
            float4 x1 = *(float4*)&sQ[e][xs + 2];
            float xr[4] = {x0.x, x0.z, x1.x, x1.z};
            float xi_[4] = {x0.y, x0.w, x1.y, x1.w};
            size_t wo = (((size_t)h * 64 + e) * 64 + os) * 64 + xs;
#pragma unroll
            for (int j = 0; j < 4; j++) {
                float4 w4r = *(const float4*)(w1r + wo + (size_t)j * 64);
                float4 w4i = *(const float4*)(w1i + wo + (size_t)j * 64);
                float wr[4] = {w4r.x, w4r.y, w4r.z, w4r.w};
                float wi[4] = {w4i.x, w4i.y, w4i.z, w4i.w};
#pragma unroll
                for (int i = 0; i < 4; i++) {
                    sre[j][i]  = fmaf(xr[i],  wr[i], sre[j][i]);
                    sre[j][i]  = fmaf(-xi_[i], wi[i], sre[j][i]);
                    sim_[j][i] = fmaf(xr[i],  wi[i], sim_[j][i]);
                    sim_[j][i] = fmaf(xi_[i], wr[i], sim_[j][i]);
                }
            }
        }
        float* sp = g_Spec + (size_t)(b * N_HE + h * N_E) * N_J;
#pragma unroll
        for (int j = 0; j < 4; j++)
#pragma unroll
            for (int i = 0; i < 4; i++)
                *(float2*)&sp[(os + j) * N_J + 2 * (xs + i)] =
                    make_float2(sre[j][i], sim_[j][i]);
    }
}

// ---------- K3: double-folded irfft ------------------------------------------
// Parity-split accs (Ce,Se)/(Co,So); 4 outputs per acc pair:
//   out[l]=Cp-Sp, out[2048-l]=Cp+Sp, out[1024-l]=Cm+Sm, out[1024+l]=Cm-Sm
// grid (16 l-tiles of 32, 256 row-tiles); 128 thr; thread 8 rows x 4 l.
__global__ void __launch_bounds__(128) k_irfft(float* __restrict__ out) {
    int l0 = blockIdx.x * 32;
    int r0 = blockIdx.y * 128;

    __shared__ __align__(16) ull sSp[16][128];  // (Re,Im) [mode][row]
    __shared__ __align__(16) ull sBp[16][32];   // (coef*cos, coef*sin) [mode][l]

    int t = threadIdx.x;
    int tr = t >> 3, tc = t & 7;
    int hs = tr * 8;

    ull accE[8][4], accO[8][4];
#pragma unroll
    for (int i = 0; i < 8; i++)
#pragma unroll
        for (int q = 0; q < 4; q++) { accE[i][q] = 0ull; accO[i][q] = 0ull; }

    for (int m0 = 0; m0 < 64; m0 += 16) {
        // Spec fill: thread t owns row r0+t (8 x LDG.128 = 16 modes)
        {
            const float* gs = g_Spec + (size_t)(r0 + t) * N_J + 2 * m0;
#pragma unroll
            for (int u = 0; u < 8; u++) {
                float4 v = *(const float4*)(gs + u * 4);
                sSp[2 * u][t]     = ((ull*)&v)[0];
                sSp[2 * u + 1][t] = ((ull*)&v)[1];
            }
        }
        // B fill: thread t loads 4 ull: mode t>>3, l offset (t&7)*4
        {
            int mm = t >> 3, li = (t & 7) * 4;
            const ull* gb = (const ull*)(g_Bip + (size_t)(m0 + mm) * BIP_W + 1 + l0 + li);
#pragma unroll
            for (int cc = 0; cc < 4; cc++) sBp[mm][li + cc] = gb[cc];
        }
        __syncthreads();
#pragma unroll 2
        for (int u = 0; u < 8; u++) {   // mode pair: 2u even, 2u+1 odd
            ull ae[8], ao[8];
#pragma unroll
            for (int hi = 0; hi < 8; hi++) {
                ae[hi] = sSp[2 * u][hs + hi];
                ao[hi] = sSp[2 * u + 1][hs + hi];
            }
            ull be[4], bo[4];
#pragma unroll
            for (int i = 0; i < 4; i++) {
                be[i] = sBp[2 * u][tc + 8 * i];
                bo[i] = sBp[2 * u + 1][tc + 8 * i];
            }
#pragma unroll
            for (int hi = 0; hi < 8; hi++)
#pragma unroll
                for (int i = 0; i < 4; i++) {
                    fma2(accE[hi][i], ae[hi], be[i]);
                    fma2(accO[hi][i], ao[hi], bo[i]);
                }
        }
        __syncthreads();
    }
#pragma unroll
    for (int hi = 0; hi < 8; hi++) {
        float* op = out + (size_t)(r0 + hs + hi) * N_L;
#pragma unroll
        for (int i = 0; i < 4; i++) {
            int l = 1 + l0 + tc + 8 * i;
            float Ce, Se, Co, So;
            upk2(Ce, Se, accE[hi][i]);
            upk2(Co, So, accO[hi][i]);
            float Cp = Ce + Co, Sp = Se + So;
            float Cm = Ce - Co, Sm = Se - So;
            if (l < 512) {
                op[l]        = Cp - Sp;
                op[2048 - l] = Cp + Sp;
                op[1024 - l] = Cm + Sm;
                op[1024 + l] = Cm - Sm;
            }
        }
    }
}

// ---------- K4: columns 0, 512, 1024, 1536 -----------------------------------
__global__ void k_edge(float* __restrict__ out) {
    int row = blockIdx.x * blockDim.x + threadIdx.x;   // 32768 rows
    const float* sp = g_Spec + (size_t)row * N_J;
    float s0 = 0.f, c5 = 0.f, s5 = 0.f, s10 = 0.f;
#pragma unroll
    for (int m = 0; m < 64; m++) {
        float re = sp[2 * m], im = sp[2 * m + 1];
        float2 b0  = g_Bip[m * BIP_W + 0];
        float2 b5  = g_Bip[m * BIP_W + 512];
        float2 b10 = g_Bip[m * BIP_W + 1024];
        s0  = fmaf(re, b0.x, s0);
        c5  = fmaf(re, b5.x, c5);
        s5  = fmaf(im, b5.y, s5);
        s10 = fmaf(re, b10.x, s10);
    }
    float* op = out + (size_t)row * N_L;
    op[0]    = s0;
    op[512]  = c5 - s5;
    op[1536] = c5 + s5;
    op[1024] = s10;
}

// ---------- launch ------------------------------------------------------------
extern "C" void kernel_launch(void* const* d_in, const int* in_sizes, int n_in,
                              void* d_out, int out_size) {
    const float* q   = (const float*)d_in[0];
    const float* k   = (const float*)d_in[1];
    const float* w1r = (const float*)d_in[3];
    const float* w1i = (const float*)d_in[4];
    float* out = (float*)d_out;

    cudaFuncSetAttribute(k_mid, cudaFuncAttributeMaxDynamicSharedMemorySize, K2_SMEM);

    k_tw<<<8, 256>>>();
    k_basis<<<512, 256>>>();
    dim3 g1(4, 64, 2);
    k_dft<<<g1, 128>>>(q, k);
    k_mid<<<512, 256, K2_SMEM>>>(w1r, w1i);
    dim3 g3(16, 256);
    k_irfft<<<g3, 128>>>(out);
    k_edge<<<128, 256>>>(out);
}

// round 12
// speedup vs baseline: 3.7920x; 1.0799x over previous
#include <cuda_runtime.h>
#include <cuda_bf16.h>
#include <cstdint>

// FourierCrossAttention: B=64, L=S=2048, H=8, E=64, MODES=64, O=64
// Double-folded DFT/irfft GEMMs + f32x2 complex middle stage.

#define N_B   64
#define N_L   2048
#define N_H   8
#define N_E   64
#define N_M   64
#define N_HE  512
#define N_J   128   // 2*N_M, interleaved (re,im)
#define BIP_W 1056  // padded row width of g_Bip (l = 0..1024 used)

typedef unsigned long long ull;

// ---------- scratch (static device globals; no runtime alloc) ----------------
__device__ double2 g_twd[N_L];             // twiddle table cos,sin (double)
__device__ float  g_Bf[N_L * N_J];         // forward basis [l][j]=(cos,-sin)
__device__ float2 g_Bip[N_M * BIP_W];      // inverse basis [m][l]=(coef*cos, coef*sin)
__device__ float g_Xq[N_B * N_HE * N_J];
__device__ float g_Xk[N_B * N_HE * N_J];
__device__ float g_Spec[N_B * N_HE * N_J];

// ---------- packed f32x2 helpers ---------------------------------------------
__device__ __forceinline__ ull pk2(float lo, float hi) {
    ull r; asm("mov.b64 %0, {%1, %2};" : "=l"(r) : "f"(lo), "f"(hi)); return r;
}
__device__ __forceinline__ void upk2(float &lo, float &hi, ull v) {
    asm("mov.b64 {%0, %1}, %2;" : "=f"(lo), "=f"(hi) : "l"(v));
}
__device__ __forceinline__ void fma2(ull &d, ull a, ull b) {
    asm("fma.rn.f32x2 %0, %1, %2, %0;" : "+l"(d) : "l"(a), "l"(b));
}
__device__ __forceinline__ void add2(ull &d, ull a) {
    asm("add.rn.f32x2 %0, %0, %1;" : "+l"(d) : "l"(a));
}

// ---------- K-1: twiddle table ------------------------------------------------
__global__ void k_tw() {
    int i = blockIdx.x * blockDim.x + threadIdx.x;   // 2048 threads
    double s, c;
    sincos((double)i * (6.283185307179586476925287 / 2048.0), &s, &c);
    g_twd[i] = make_double2(c, s);
}

// ---------- K0: basis tables --------------------------------------------------
__global__ void k_basis() {
    int idx = blockIdx.x * blockDim.x + threadIdx.x;   // 64*2048 threads
    int m = idx >> 11;
    int l = idx & 2047;
    double2 t = g_twd[(m * l) & 2047];
    g_Bf[l * N_J + 2 * m]     = (float)t.x;
    g_Bf[l * N_J + 2 * m + 1] = (float)(-t.y);
    if (l < BIP_W) {
        double coef = (m == 0 ? 1.0 : 2.0) / (2048.0 * 512.0 * 512.0);
        float2 v = (l <= 1024)
                 ? make_float2((float)(coef * t.x), (float)(coef * t.y))
                 : make_float2(0.0f, 0.0f);
        g_Bip[m * BIP_W + l] = v;
    }
}

// ---------- K1: double-folded DFT, K=512, double-buffered pipeline -----------
// dynamic smem layout (82944 B):
//   sGE  [2*16][128] ull   @ 0
//   sGO  [2*16][128] ull   @ 32768
//   sB   [2*16][128] float @ 65536
//   sE   [2*128]     float @ 81920
#define DFT_SMEM 82944
__global__ void __launch_bounds__(128) k_dft(const float* __restrict__ qp,
                                             const float* __restrict__ kp) {
    extern __shared__ char dsm[];
    ull   (*sGE)[128] = (ull(*)[128])(dsm);
    ull   (*sGO)[128] = (ull(*)[128])(dsm + 32768);
    float (*sB)[128]  = (float(*)[128])(dsm + 65536);
    float *sE         = (float*)(dsm + 81920);

    const float* src = blockIdx.z ? kp : qp;
    float* dst       = blockIdx.z ? g_Xk : g_Xq;
    int b = blockIdx.y;
    int he0 = blockIdx.x * 128;

    int t = threadIdx.x;
    int w = t >> 5, lane = t & 31;
    int tr = t >> 3, tc = t & 7;
    int hs = tr * 8;

    ull acc[8][8];
#pragma unroll
    for (int i = 0; i < 8; i++)
#pragma unroll
        for (int q = 0; q < 8; q++) acc[i][q] = 0ull;

    const float* abase = src + (size_t)b * N_L * N_HE + he0;

    if (t < 32) {
        *(float4*)&sE[t * 4] = *(const float4*)(abase + t * 4);
        *(float4*)&sE[128 + t * 4] =
            *(const float4*)(abase + (size_t)1024 * N_HE + t * 4);
    }

    float4 X[4][4];   // [rr][{l, 2048-l, 1024-l, 1024+l}]
    float4 Bv[4];

    // --- fill helpers (macro-free, inlined by unrolling) ---
    auto fill_load = [&](int tile) {
        int lb = 1 + tile * 16;
#pragma unroll
        for (int rr = 0; rr < 4; rr++) {
            int l = lb + w + rr * 4;
            X[rr][0] = *(const float4*)(abase + (size_t)l * N_HE + lane * 4);
            X[rr][1] = *(const float4*)(abase + (size_t)(2048 - l) * N_HE + lane * 4);
            X[rr][2] = *(const float4*)(abase + (size_t)(1024 - l) * N_HE + lane * 4);
            X[rr][3] = *(const float4*)(abase + (size_t)(1024 + l) * N_HE + lane * 4);
            Bv[rr]   = *(const float4*)(g_Bf + (size_t)l * N_J + lane * 4);
        }
    };
    auto fill_store = [&](int tile, int pn) {
        int lb = 1 + tile * 16;
#pragma unroll
        for (int rr = 0; rr < 4; rr++) {
            int row = w + rr * 4;
            int l = lb + row;
            float h = (l == 512) ? 0.5f : 1.0f;
            const float* a    = (const float*)&X[rr][0];
            const float* rmir = (const float*)&X[rr][1];
            const float* mmir = (const float*)&X[rr][2];
            const float* pmir = (const float*)&X[rr][3];
#pragma unroll
            for (int cc = 0; cc < 4; cc++) {
                float fp = a[cc] + rmir[cc];
                float fm = a[cc] - rmir[cc];
                float fq = mmir[cc] + pmir[cc];
                float fn = mmir[cc] - pmir[cc];
                sGE[pn * 16 + row][lane * 4 + cc] = pk2(h * (fp + fq), h * (fm - fn));
                sGO[pn * 16 + row][lane * 4 + cc] = pk2(h * (fp - fq), h * (fm + fn));
            }
            *(float4*)&sB[pn * 16 + row][lane * 4] = Bv[rr];
        }
    };

    fill_load(0);
    fill_store(0, 0);
    __syncthreads();

    for (int tile = 0; tile < 32; tile++) {
        int p = tile & 1;
        if (tile < 31) fill_load(tile + 1);          // LDGs overlap compute below
        const ull (*gsel)[128] = (tc & 1) ? (sGO + p * 16) : (sGE + p * 16);
        const float (*bsel)[128] = sB + p * 16;
#pragma unroll 4
        for (int kk = 0; kk < 16; kk++) {
            ull aa[8];
#pragma unroll
            for (int hi = 0; hi < 8; hi++) aa[hi] = gsel[kk][hs + hi];
            ull bb[8];
#pragma unroll
            for (int i = 0; i < 8; i++)
                bb[i] = *(ull*)&bsel[kk][2 * (tc + 8 * i)];
#pragma unroll
            for (int hi = 0; hi < 8; hi++)
#pragma unroll
                for (int i = 0; i < 8; i++)
                    fma2(acc[hi][i], aa[hi], bb[i]);
        }
        if (tile < 31) fill_store(tile + 1, p ^ 1);
        __syncthreads();
    }
    // epilogue: l=0 adds x0 to Re (all m); l=1024 adds (-1)^m * x1024 to Re
    float sgn = (tc & 1) ? -1.0f : 1.0f;
#pragma unroll
    for (int hi = 0; hi < 8; hi++) {
        ull e = pk2(sE[hs + hi] + sgn * sE[128 + hs + hi], 0.0f);
#pragma unroll
        for (int i = 0; i < 8; i++) add2(acc[hi][i], e);
    }
#pragma unroll
    for (int hi = 0; hi < 8; hi++) {
        float* dp = dst + (size_t)(b * N_HE + he0 + hs + hi) * N_J;
#pragma unroll
        for (int i = 0; i < 8; i++)
            *(ull*)&dp[2 * (tc + 8 * i)] = acc[hi][i];
    }
}

// ---------- complex tanh: fast saturated path + stable double fallback -------
__device__ __forceinline__ float2 ctanh_c(float re, float im) {
    if (fabsf(re) > 9.5f)
        return make_float2(re > 0.0f ? 1.0f : -1.0f, 0.0f);
    double tx = tanh((double)re);
    double ty = tan((double)im);
    double tx2 = tx * tx, ty2 = ty * ty;
    double inv = 1.0 / (1.0 + tx2 * ty2);
    return make_float2((float)(tx * (1.0 + ty2) * inv),
                       (float)(ty * (1.0 - tx2) * inv));
}

// ---------- K2: fused middle stage, f32x2 deferred-combine -------------------
// acc1 += (re,im)*(c,c); acc2 += (re,im)*(d,d);  out_re = a1.lo - a2.hi,
// out_im = a1.hi + a2.lo  (c = partner re, d = partner im).
#define K2_SMEM (3 * 64 * 66 * (int)sizeof(float2))
__global__ void __launch_bounds__(256, 2) k_mid(const float* __restrict__ w1r,
                                                const float* __restrict__ w1i) {
    int bh = blockIdx.x;
    int b = bh >> 3, h = bh & 7;
    extern __shared__ float2 sm2[];
    float2 (*sQ)[66] = (float2(*)[66])sm2;
    float2 (*sK)[66] = ((float2(*)[66])sm2) + 64;
    float2 (*sA)[66] = ((float2(*)[66])sm2) + 128;

    int t = threadIdx.x;
    int r = t >> 4, c = t & 15;
    int xs = c * 4;

    const float* xqb = g_Xq + (size_t)(b * N_HE + h * N_E) * N_J;
    const float* xkb = g_Xk + (size_t)(b * N_HE + h * N_E) * N_J;
    for (int i = t; i < 64 * 32; i += 256) {
        int row = i >> 5, c4 = i & 31;
        *(float4*)&sQ[row][c4 * 2] = *(const float4*)(xqb + row * N_J + c4 * 4);
        *(float4*)&sK[row][c4 * 2] = *(const float4*)(xkb + row * N_J + c4 * 4);
    }
    __syncthreads();

    // stage A: A[x][y] = tanh( sum_e Xq[e][x]*Xk[e][y] )
    {
        int ys = r * 4;
        ull a1[4][4], a2[4][4];
#pragma unroll
        for (int i = 0; i < 4; i++)
#pragma unroll
            for (int j = 0; j < 4; j++) { a1[i][j] = 0ull; a2[i][j] = 0ull; }
        for (int e = 0; e < 64; e++) {
            ulonglong2 q01 = *(ulonglong2*)&sQ[e][xs];
            ulonglong2 q23 = *(ulonglong2*)&sQ[e][xs + 2];
            ull qp[4] = {q01.x, q01.y, q23.x, q23.y};
            float4 kA = *(float4*)&sK[e][ys];
            float4 kB = *(float4*)&sK[e][ys + 2];
            ull krr[4] = {pk2(kA.x, kA.x), pk2(kA.z, kA.z),
                          pk2(kB.x, kB.x), pk2(kB.z, kB.z)};
            ull kii[4] = {pk2(kA.y, kA.y), pk2(kA.w, kA.w),
                          pk2(kB.y, kB.y), pk2(kB.w, kB.w)};
#pragma unroll
            for (int i = 0; i < 4; i++)
#pragma unroll
                for (int j = 0; j < 4; j++) {
                    fma2(a1[i][j], qp[i], krr[j]);
                    fma2(a2[i][j], qp[i], kii[j]);
                }
        }
#pragma unroll
        for (int i = 0; i < 4; i++)
#pragma unroll
            for (int j = 0; j < 4; j++) {
                float s1l, s1h, s2l, s2h;
                upk2(s1l, s1h, a1[i][j]);
                upk2(s2l, s2h, a2[i][j]);
                sA[ys + j][xs + i] = ctanh_c(s1l - s2h, s1h + s2l);
            }
    }
    __syncthreads();

    // stage B: Xqkv[e][x] = sum_y A[x][y]*Xk[e][y]   -> overwrite sQ
    {
        int es = r * 4;
        ull b1[4][4], b2[4][4];   // [ei][xi]
#pragma unroll
        for (int i = 0; i < 4; i++)
#pragma unroll
            for (int j = 0; j < 4; j++) { b1[i][j] = 0ull; b2[i][j] = 0ull; }
        for (int y = 0; y < 64; y++) {
            ulonglong2 A01 = *(ulonglong2*)&sA[y][xs];
            ulonglong2 A23 = *(ulonglong2*)&sA[y][xs + 2];
            ull ap[4] = {A01.x, A01.y, A23.x, A23.y};
            float2 kv[4];
#pragma unroll
            for (int j = 0; j < 4; j++) kv[j] = sK[es + j][y];
            ull krr[4] = {pk2(kv[0].x, kv[0].x), pk2(kv[1].x, kv[1].x),
                          pk2(kv[2].x, kv[2].x), pk2(kv[3].x, kv[3].x)};
            ull kii[4] = {pk2(kv[0].y, kv[0].y), pk2(kv[1].y, kv[1].y),
                          pk2(kv[2].y, kv[2].y), pk2(kv[3].y, kv[3].y)};
#pragma unroll
            for (int ei = 0; ei < 4; ei++)
#pragma unroll
                for (int xi = 0; xi < 4; xi++) {
                    fma2(b1[ei][xi], ap[xi], krr[ei]);
                    fma2(b2[ei][xi], ap[xi], kii[ei]);
                }
        }
        __syncthreads();
#pragma unroll
        for (int ei = 0; ei < 4; ei++)
#pragma unroll
            for (int xi = 0; xi < 4; xi++) {
                float s1l, s1h, s2l, s2h;
                upk2(s1l, s1h, b1[ei][xi]);
                upk2(s2l, s2h, b2[ei][xi]);
                sQ[es + ei][xs + xi] = make_float2(s1l - s2h, s1h + s2l);
            }
    }
    __syncthreads();

    // stage C: Spec[o][x] = sum_e Xqkv[e][x] * w[h,e,o,x]
    {
        int os = r * 4;
        ull c1[4][4], c2[4][4];   // [o][x]
#pragma unroll
        for (int i = 0; i < 4; i++)
#pragma unroll
            for (int j = 0; j < 4; j++) { c1[i][j] = 0ull; c2[i][j] = 0ull; }
        for (int e = 0; e < 64; e++) {
            ulonglong2 X01 = *(ulonglong2*)&sQ[e][xs];
            ulonglong2 X23 = *(ulonglong2*)&sQ[e][xs + 2];
            ull xp[4] = {X01.x, X01.y, X23.x, X23.y};
            size_t wo = (((size_t)h * 64 + e) * 64 + os) * 64 + xs;
#pragma unroll
            for (int j = 0; j < 4; j++) {
                float4 w4r = *(const float4*)(w1r + wo + (size_t)j * 64);
                float4 w4i = *(const float4*)(w1i + wo + (size_t)j * 64);
                const float* wr = (const float*)&w4r;
                const float* wi = (const float*)&w4i;
#pragma unroll
                for (int i = 0; i < 4; i++) {
                    fma2(c1[j][i], xp[i], pk2(wr[i], wr[i]));
                    fma2(c2[j][i], xp[i], pk2(wi[i], wi[i]));
                }
            }
        }
        float* sp = g_Spec + (size_t)(b * N_HE + h * N_E) * N_J;
#pragma unroll
        for (int j = 0; j < 4; j++)
#pragma unroll
            for (int i = 0; i < 4; i++) {
                float s1l, s1h, s2l, s2h;
                upk2(s1l, s1h, c1[j][i]);
                upk2(s2l, s2h, c2[j][i]);
                *(float2*)&sp[(os + j) * N_J + 2 * (xs + i)] =
                    make_float2(s1l - s2h, s1h + s2l);
            }
    }
}

// ---------- K3: double-folded irfft ------------------------------------------
__global__ void __launch_bounds__(128) k_irfft(float* __restrict__ out) {
    int l0 = blockIdx.x * 32;
    int r0 = blockIdx.y * 128;

    __shared__ __align__(16) ull sSp[16][128];  // (Re,Im) [mode][row]
    __shared__ __align__(16) ull sBp[16][32];   // (coef*cos, coef*sin) [mode][l]

    int t = threadIdx.x;
    int tr = t >> 3, tc = t & 7;
    int hs = tr * 8;

    ull accE[8][4], accO[8][4];
#pragma unroll
    for (int i = 0; i < 8; i++)
#pragma unroll
        for (int q = 0; q < 4; q++) { accE[i][q] = 0ull; accO[i][q] = 0ull; }

    for (int m0 = 0; m0 < 64; m0 += 16) {
        {
            const float* gs = g_Spec + (size_t)(r0 + t) * N_J + 2 * m0;
#pragma unroll
            for (int u = 0; u < 8; u++) {
                float4 v = *(const float4*)(gs + u * 4);
                sSp[2 * u][t]     = ((ull*)&v)[0];
                sSp[2 * u + 1][t] = ((ull*)&v)[1];
            }
        }
        {
            int mm = t >> 3, li = (t & 7) * 4;
            const ull* gb = (const ull*)(g_Bip + (size_t)(m0 + mm) * BIP_W + 1 + l0 + li);
#pragma unroll
            for (int cc = 0; cc < 4; cc++) sBp[mm][li + cc] = gb[cc];
        }
        __syncthreads();
#pragma unroll 2
        for (int u = 0; u < 8; u++) {
            ull ae[8], ao[8];
#pragma unroll
            for (int hi = 0; hi < 8; hi++) {
                ae[hi] = sSp[2 * u][hs + hi];
                ao[hi] = sSp[2 * u + 1][hs + hi];
            }
            ull be[4], bo[4];
#pragma unroll
            for (int i = 0; i < 4; i++) {
                be[i] = sBp[2 * u][tc + 8 * i];
                bo[i] = sBp[2 * u + 1][tc + 8 * i];
            }
#pragma unroll
            for (int hi = 0; hi < 8; hi++)
#pragma unroll
                for (int i = 0; i < 4; i++) {
                    fma2(accE[hi][i], ae[hi], be[i]);
                    fma2(accO[hi][i], ao[hi], bo[i]);
                }
        }
        __syncthreads();
    }
#pragma unroll
    for (int hi = 0; hi < 8; hi++) {
        float* op = out + (size_t)(r0 + hs + hi) * N_L;
#pragma unroll
        for (int i = 0; i < 4; i++) {
            int l = 1 + l0 + tc + 8 * i;
            float Ce, Se, Co, So;
            upk2(Ce, Se, accE[hi][i]);
            upk2(Co, So, accO[hi][i]);
            float Cp = Ce + Co, Sp = Se + So;
            float Cm = Ce - Co, Sm = Se - So;
            if (l < 512) {
                op[l]        = Cp - Sp;
                op[2048 - l] = Cp + Sp;
                op[1024 - l] = Cm + Sm;
                op[1024 + l] = Cm - Sm;
            }
        }
    }
}

// ---------- K4: columns 0, 512, 1024, 1536 -----------------------------------
__global__ void k_edge(float* __restrict__ out) {
    int row = blockIdx.x * blockDim.x + threadIdx.x;   // 32768 rows
    const float* sp = g_Spec + (size_t)row * N_J;
    float s0 = 0.f, c5 = 0.f, s5 = 0.f, s10 = 0.f;
#pragma unroll
    for (int m = 0; m < 64; m++) {
        float re = sp[2 * m], im = sp[2 * m + 1];
        float2 b0  = g_Bip[m * BIP_W + 0];
        float2 b5  = g_Bip[m * BIP_W + 512];
        float2 b10 = g_Bip[m * BIP_W + 1024];
        s0  = fmaf(re, b0.x, s0);
        c5  = fmaf(re, b5.x, c5);
        s5  = fmaf(im, b5.y, s5);
        s10 = fmaf(re, b10.x, s10);
    }
    float* op = out + (size_t)row * N_L;
    op[0]    = s0;
    op[512]  = c5 - s5;
    op[1536] = c5 + s5;
    op[1024] = s10;
}

// ---------- launch ------------------------------------------------------------
extern "C" void kernel_launch(void* const* d_in, const int* in_sizes, int n_in,
                              void* d_out, int out_size) {
    const float* q   = (const float*)d_in[0];
    const float* k   = (const float*)d_in[1];
    const float* w1r = (const float*)d_in[3];
    const float* w1i = (const float*)d_in[4];
    float* out = (float*)d_out;

    cudaFuncSetAttribute(k_mid, cudaFuncAttributeMaxDynamicSharedMemorySize, K2_SMEM);
    cudaFuncSetAttribute(k_dft, cudaFuncAttributeMaxDynamicSharedMemorySize, DFT_SMEM);

    k_tw<<<8, 256>>>();
    k_basis<<<512, 256>>>();
    dim3 g1(4, 64, 2);
    k_dft<<<g1, 128, DFT_SMEM>>>(q, k);
    k_mid<<<512, 256, K2_SMEM>>>(w1r, w1i);
    dim3 g3(16, 256);
    k_irfft<<<g3, 128>>>(out);
    k_edge<<<128, 256>>>(out);
}